// round 11
// baseline (speedup 1.0000x reference)
#include <cuda_runtime.h>
#include <cuda_bf16.h>

// B=16, N_VEC=2048, N_DIM=32, N_W=4, N_HID=128, VOCAB=32000, N_CLASS=10

__device__ __forceinline__ unsigned f2tf32(float x) {
    unsigned r;
    asm("cvt.rna.tf32.f32 %0, %1;" : "=r"(r) : "f"(x));
    return r;
}
__device__ __forceinline__ void mma_tf32(float* c, const unsigned* a, const unsigned* b) {
    asm volatile(
        "mma.sync.aligned.m16n8k8.row.col.f32.tf32.tf32.f32 "
        "{%0,%1,%2,%3}, {%4,%5,%6,%7}, {%8,%9}, {%0,%1,%2,%3};"
        : "+f"(c[0]), "+f"(c[1]), "+f"(c[2]), "+f"(c[3])
        : "r"(a[0]), "r"(a[1]), "r"(a[2]), "r"(a[3]), "r"(b[0]), "r"(b[1]));
}

// ---------- scratch (device globals; allocation is forbidden) ----------
__device__ float g_X [16 * 2048 * 32];
__device__ float g_VA[16 * 2048 * 32];
__device__ float g_VB[16 * 2048 * 32];
__device__ float g_Upart[16 * 16 * 129 * 32];
__device__ float g_U[16 * 129 * 32];
__device__ float g_partF[16 * 32 * 10];
__device__ unsigned g_tick;
// pre-split tf32 hi/lo copies (producer-side conversion)
__device__ unsigned g_fw1h[4 * 32 * 128],   g_fw1l[4 * 32 * 128];
__device__ unsigned g_fw2h[4 * 128 * 2048], g_fw2l[4 * 128 * 2048];
__device__ unsigned g_Xh[16 * 2048 * 32],   g_Xl[16 * 2048 * 32];
__device__ unsigned g_Uh[16 * 128 * 32],    g_Ul[16 * 128 * 32];

// ---------- one-shot weight split ----------
__global__ __launch_bounds__(256) void k_wsplit(const float* __restrict__ fw1,
                                                const float* __restrict__ fw2) {
    int idx = blockIdx.x * 256 + threadIdx.x;
    if (idx < 16384) {
        float v = fw1[idx];
        unsigned h = f2tf32(v);
        g_fw1h[idx] = h;
        g_fw1l[idx] = f2tf32(v - __uint_as_float(h));
    } else {
        int i2 = idx - 16384;
        if (i2 < 1048576) {
            float v = fw2[i2];
            unsigned h = f2tf32(v);
            g_fw2h[i2] = h;
            g_fw2l[i2] = f2tf32(v - __uint_as_float(h));
        }
    }
}

// ---------- X = emb[data] (+ tf32 split), per-block int64/int32 detection ----------
__global__ __launch_bounds__(256) void k_gather(const int* __restrict__ d32,
                                                const float* __restrict__ emb) {
    __shared__ int s_is64;
    int tid = threadIdx.x;
    if (tid == 0) s_is64 = 1;
    __syncthreads();
    if (tid < 32) { if (d32[2 * tid + 1] != 0) s_is64 = 0; }
    __syncthreads();
    int t = blockIdx.x * 256 + tid;
    int row = t >> 3, q = t & 7;
    int idx = s_is64 ? d32[row * 2] : d32[row];
    float4 v = *reinterpret_cast<const float4*>(emb + (size_t)idx * 32 + q * 4);
    size_t o = (size_t)row * 32 + q * 4;
    *reinterpret_cast<float4*>(g_X + o) = v;
    uint4 h, l;
    h.x = f2tf32(v.x); l.x = f2tf32(v.x - __uint_as_float(h.x));
    h.y = f2tf32(v.y); l.y = f2tf32(v.y - __uint_as_float(h.y));
    h.z = f2tf32(v.z); l.z = f2tf32(v.z - __uint_as_float(h.z));
    h.w = f2tf32(v.w); l.w = f2tf32(v.w - __uint_as_float(h.w));
    *reinterpret_cast<uint4*>(g_Xh + o) = h;
    *reinterpret_cast<uint4*>(g_Xl + o) = l;
}

// ---------- U partials via TF32 tensor cores (A pre-split) ----------
__global__ __launch_bounds__(256) void k_upart(const float* __restrict__ fb2,
                                               int vin_sel, int layer) {
    __shared__ unsigned Bh[128 * 40];
    __shared__ unsigned Bl[128 * 40];
    __shared__ float   Sfb[128];
    int b = blockIdx.y, ch = blockIdx.x, tid = threadIdx.x;
    int m0 = ch * 128;
    const float* Vin = (vin_sel == 0) ? g_X : (vin_sel == 1 ? g_VA : g_VB);
    const float4* vg4 = reinterpret_cast<const float4*>(Vin + ((size_t)(b * 2048 + m0)) * 32);

#pragma unroll
    for (int it = 0; it < 4; ++it) {
        int t4 = tid + it * 256;
        int m = t4 >> 3, dq = (t4 & 7) * 4;
        float4 v = vg4[t4];
        unsigned* ph = Bh + m * 40 + dq;
        unsigned* pl = Bl + m * 40 + dq;
        unsigned h;
        h = f2tf32(v.x); ph[0] = h; pl[0] = f2tf32(v.x - __uint_as_float(h));
        h = f2tf32(v.y); ph[1] = h; pl[1] = f2tf32(v.y - __uint_as_float(h));
        h = f2tf32(v.z); ph[2] = h; pl[2] = f2tf32(v.z - __uint_as_float(h));
        h = f2tf32(v.w); ph[3] = h; pl[3] = f2tf32(v.w - __uint_as_float(h));
    }
    if (tid < 128) Sfb[tid] = fb2[(size_t)layer * 2048 + m0 + tid];
    __syncthreads();

    int w = tid >> 5, lane = tid & 31;
    int grp = lane >> 2, tig = lane & 3;
    size_t abase = ((size_t)(layer * 128 + w * 16 + grp)) * 2048 + m0;
    const unsigned* A0h = g_fw2h + abase;
    const unsigned* A8h = A0h + 8 * 2048;
    const unsigned* A0l = g_fw2l + abase;
    const unsigned* A8l = A0l + 8 * 2048;

    float accM[4][4], accC[4][4];
#pragma unroll
    for (int nt = 0; nt < 4; ++nt)
#pragma unroll
        for (int i = 0; i < 4; ++i) { accM[nt][i] = 0.f; accC[nt][i] = 0.f; }

#pragma unroll 4
    for (int ks = 0; ks < 16; ++ks) {
        int c0 = ks * 8 + tig;
        unsigned ah[4] = { A0h[c0], A8h[c0], A0h[c0 + 4], A8h[c0 + 4] };
        unsigned al[4] = { A0l[c0], A8l[c0], A0l[c0 + 4], A8l[c0 + 4] };
        const unsigned* rh0 = Bh + (ks * 8 + tig) * 40 + grp;
        const unsigned* rh4 = rh0 + 4 * 40;
        const unsigned* rl0 = Bl + (ks * 8 + tig) * 40 + grp;
        const unsigned* rl4 = rl0 + 4 * 40;
#pragma unroll
        for (int nt = 0; nt < 4; ++nt) {
            unsigned bh[2] = { rh0[nt * 8], rh4[nt * 8] };
            unsigned bl[2] = { rl0[nt * 8], rl4[nt * 8] };
            mma_tf32(accM[nt], ah, bh);
            mma_tf32(accC[nt], al, bh);
            mma_tf32(accC[nt], ah, bl);
        }
    }

    float* up = g_Upart + (((size_t)(b * 16 + ch)) * 129 + w * 16) * 32;
#pragma unroll
    for (int nt = 0; nt < 4; ++nt) {
        int d = nt * 8 + tig * 2;
        float2 r0 = make_float2(accM[nt][0] + accC[nt][0], accM[nt][1] + accC[nt][1]);
        float2 r1 = make_float2(accM[nt][2] + accC[nt][2], accM[nt][3] + accC[nt][3]);
        *reinterpret_cast<float2*>(up + grp * 32 + d) = r0;
        *reinterpret_cast<float2*>(up + (grp + 8) * 32 + d) = r1;
    }

    if (w == 0) {
        float acc = 0.f;
#pragma unroll 8
        for (int m = 0; m < 128; ++m)
            acc += Sfb[m] * (__uint_as_float(Bh[m * 40 + lane]) +
                             __uint_as_float(Bl[m * 40 + lane]));
        g_Upart[(((size_t)(b * 16 + ch)) * 129 + 128) * 32 + lane] = acc;
    }
}

// ---------- reduce split-K partials (+ tf32 split of U) ----------
__global__ __launch_bounds__(256) void k_ured() {
    int idx = blockIdx.x * 256 + threadIdx.x;
    if (idx >= 16 * 1032) return;
    int b = idx / 1032, r4 = idx - b * 1032;
    const float4* base = reinterpret_cast<const float4*>(g_Upart) + (size_t)b * 16 * 1032 + r4;
    float4 s = make_float4(0.f, 0.f, 0.f, 0.f);
#pragma unroll
    for (int c = 0; c < 16; ++c) {
        float4 v = base[(size_t)c * 1032];
        s.x += v.x; s.y += v.y; s.z += v.z; s.w += v.w;
    }
    reinterpret_cast<float4*>(g_U)[(size_t)b * 1032 + r4] = s;
    if (r4 < 1024) {
        uint4 h, l;
        h.x = f2tf32(s.x); l.x = f2tf32(s.x - __uint_as_float(h.x));
        h.y = f2tf32(s.y); l.y = f2tf32(s.y - __uint_as_float(h.y));
        h.z = f2tf32(s.z); l.z = f2tf32(s.z - __uint_as_float(h.z));
        h.w = f2tf32(s.w); l.w = f2tf32(s.w - __uint_as_float(h.w));
        reinterpret_cast<uint4*>(g_Uh)[(size_t)b * 1024 + r4] = h;
        reinterpret_cast<uint4*>(g_Ul)[(size_t)b * 1024 + r4] = l;
    }
}

// ---------- fused tensor-core vupd: all operands pre-split, smem = H only ----------
// 32 rows/block, 128 threads (4 warps), grid (64,16). 34.4KB static smem.
__global__ __launch_bounds__(128) void k_vupd(const float* __restrict__ fb1,
                                              int vout_sel, int layer) {
    __shared__ unsigned Hh[32 * 132], Hl[32 * 132];
    __shared__ float crow[32], fb1s[128];
    int b = blockIdx.y, n0 = blockIdx.x * 32, tid = threadIdx.x;

    if (tid < 32) crow[tid] = g_U[(size_t)b * 4128 + 4096 + tid];
    fb1s[tid] = fb1[layer * 128 + tid];
    __syncthreads();

    int w = tid >> 5, lane = tid & 31;
    int grp = lane >> 2, tig = lane & 3;
    int mtb = (w & 1) * 16;
    int ntb = (w >> 1) * 8;

    // ---- GEMM1: C1[32r x 128j] = X @ fw1 (all fragments direct LDG, pre-split) ----
    float c1M[8][4], c1C[8][4];
#pragma unroll
    for (int nt = 0; nt < 8; ++nt)
#pragma unroll
        for (int i = 0; i < 4; ++i) { c1M[nt][i] = 0.f; c1C[nt][i] = 0.f; }

    size_t xbase = ((size_t)(b * 2048 + n0 + mtb + grp)) * 32;
    const unsigned* X0h = g_Xh + xbase;
    const unsigned* X8h = X0h + 8 * 32;
    const unsigned* X0l = g_Xl + xbase;
    const unsigned* X8l = X0l + 8 * 32;
    const unsigned* Wh = g_fw1h + (size_t)layer * 4096;
    const unsigned* Wl = g_fw1l + (size_t)layer * 4096;
#pragma unroll
    for (int ks = 0; ks < 4; ++ks) {
        int k0 = 8 * ks + tig;
        unsigned ah[4] = { X0h[k0], X8h[k0], X0h[k0 + 4], X8h[k0 + 4] };
        unsigned al[4] = { X0l[k0], X8l[k0], X0l[k0 + 4], X8l[k0 + 4] };
        const unsigned* Wr0h = Wh + (size_t)k0 * 128;
        const unsigned* Wr4h = Wh + (size_t)(k0 + 4) * 128;
        const unsigned* Wr0l = Wl + (size_t)k0 * 128;
        const unsigned* Wr4l = Wl + (size_t)(k0 + 4) * 128;
#pragma unroll
        for (int nt = 0; nt < 8; ++nt) {
            int j = (ntb + nt) * 8 + grp;
            unsigned bh[2] = { Wr0h[j], Wr4h[j] };
            unsigned bl[2] = { Wr0l[j], Wr4l[j] };
            mma_tf32(c1M[nt], ah, bh);
            mma_tf32(c1C[nt], al, bh);
            mma_tf32(c1C[nt], ah, bl);
        }
    }

    // ---- bias + exact GELU in-register, write H hi/lo to smem ----
#pragma unroll
    for (int nt = 0; nt < 8; ++nt) {
        int j0 = (ntb + nt) * 8 + tig * 2;
        float bj0 = fb1s[j0], bj1 = fb1s[j0 + 1];
#pragma unroll
        for (int hf = 0; hf < 2; ++hf) {
            int r = mtb + grp + hf * 8;
            float v0 = c1M[nt][hf * 2] + c1C[nt][hf * 2] + bj0;
            float v1 = c1M[nt][hf * 2 + 1] + c1C[nt][hf * 2 + 1] + bj1;
            float h0 = 0.5f * v0 * (1.0f + erff(v0 * 0.70710678118654752f));
            float h1 = 0.5f * v1 * (1.0f + erff(v1 * 0.70710678118654752f));
            unsigned hh0 = f2tf32(h0), hh1 = f2tf32(h1);
            unsigned lo0 = f2tf32(h0 - __uint_as_float(hh0));
            unsigned lo1 = f2tf32(h1 - __uint_as_float(hh1));
            *reinterpret_cast<uint2*>(Hh + r * 132 + j0) = make_uint2(hh0, hh1);
            *reinterpret_cast<uint2*>(Hl + r * 132 + j0) = make_uint2(lo0, lo1);
        }
    }
    __syncthreads();

    // ---- GEMM2: V'[32r x 32d] = H @ U + crow (U direct LDG, pre-split) ----
    int ntb2 = (w >> 1) * 2;
    float c2M[2][4], c2C[2][4];
#pragma unroll
    for (int nt = 0; nt < 2; ++nt)
#pragma unroll
        for (int i = 0; i < 4; ++i) { c2M[nt][i] = 0.f; c2C[nt][i] = 0.f; }

    int ra = (mtb + grp) * 132;
    int rb = ra + 8 * 132;
    const unsigned* Ubh = g_Uh + (size_t)b * 4096;
    const unsigned* Ubl = g_Ul + (size_t)b * 4096;
#pragma unroll 4
    for (int ks = 0; ks < 16; ++ks) {
        int k0 = 8 * ks + tig;
        unsigned ah[4] = { Hh[ra + k0], Hh[rb + k0], Hh[ra + k0 + 4], Hh[rb + k0 + 4] };
        unsigned al[4] = { Hl[ra + k0], Hl[rb + k0], Hl[ra + k0 + 4], Hl[rb + k0 + 4] };
#pragma unroll
        for (int nt = 0; nt < 2; ++nt) {
            int n = (ntb2 + nt) * 8 + grp;
            unsigned bh[2] = { Ubh[k0 * 32 + n], Ubh[(k0 + 4) * 32 + n] };
            unsigned bl[2] = { Ubl[k0 * 32 + n], Ubl[(k0 + 4) * 32 + n] };
            mma_tf32(c2M[nt], ah, bh);
            mma_tf32(c2C[nt], al, bh);
            mma_tf32(c2C[nt], ah, bl);
        }
    }

    float* Vout = (vout_sel == 1) ? g_VA : g_VB;
#pragma unroll
    for (int nt = 0; nt < 2; ++nt) {
        int d0 = (ntb2 + nt) * 8 + tig * 2;
        float cc0 = crow[d0], cc1 = crow[d0 + 1];
#pragma unroll
        for (int hf = 0; hf < 2; ++hf) {
            int r = n0 + mtb + grp + hf * 8;
            float2 o = make_float2(c2M[nt][hf * 2] + c2C[nt][hf * 2] + cc0,
                                   c2M[nt][hf * 2 + 1] + c2C[nt][hf * 2 + 1] + cc1);
            *reinterpret_cast<float2*>(Vout + ((size_t)(b * 2048 + r)) * 32 + d0) = o;
        }
    }
}

// ---------- final projection, fused partial + completion (ticket) ----------
__global__ __launch_bounds__(256) void k_fproj(const float* __restrict__ Wf,
                                               const float* __restrict__ bf,
                                               float* __restrict__ out) {
    __shared__ float wsum[8][10];
    __shared__ int s_last;
    int b = blockIdx.y, ch = blockIdx.x, tid = threadIdx.x;
    int lane = tid & 31, w = tid >> 5;
    float acc[10];
#pragma unroll
    for (int c = 0; c < 10; ++c) acc[c] = 0.f;
    const float* Vb = g_VB + (size_t)b * 65536 + ch * 2048;
#pragma unroll
    for (int q = 0; q < 8; ++q) {
        int k = q * 256 + tid;
        float v = Vb[k];
        const float* wr = Wf + (size_t)(ch * 2048 + k) * 10;
#pragma unroll
        for (int c = 0; c < 10; ++c) acc[c] += v * wr[c];
    }
#pragma unroll
    for (int c = 0; c < 10; ++c) {
#pragma unroll
        for (int s = 16; s > 0; s >>= 1) acc[c] += __shfl_down_sync(0xffffffffu, acc[c], s);
        if (lane == 0) wsum[w][c] = acc[c];
    }
    __syncthreads();
    if (tid < 10) {
        float s = 0.f;
#pragma unroll
        for (int ww = 0; ww < 8; ++ww) s += wsum[ww][tid];
        g_partF[((size_t)(b * 32 + ch)) * 10 + tid] = s;
    }
    __threadfence();
    __syncthreads();
    if (tid == 0) {
        unsigned prev = atomicAdd(&g_tick, 1u);
        s_last = (prev == 511u) ? 1 : 0;
    }
    __syncthreads();
    if (s_last) {
        __threadfence();
        if (tid < 160) {
            int bb = tid / 10, c = tid % 10;
            float s = bf[c];
#pragma unroll
            for (int cc = 0; cc < 32; ++cc) s += g_partF[((size_t)(bb * 32 + cc)) * 10 + c];
            out[tid] = s;
        }
        if (tid == 0) g_tick = 0u;
    }
}

extern "C" void kernel_launch(void* const* d_in, const int* in_sizes, int n_in,
                              void* d_out, int out_size) {
    const int*   data = (const int*)  d_in[0];
    const float* emb  = (const float*)d_in[1];
    const float* fw1  = (const float*)d_in[2];
    const float* fb1  = (const float*)d_in[3];
    const float* fb2  = (const float*)d_in[5];
    const float* Wf   = (const float*)d_in[6];
    const float* bf   = (const float*)d_in[7];
    const float* fw2  = (const float*)d_in[4];
    float* out = (float*)d_out;

    k_wsplit<<<4161, 256>>>(fw1, fw2);
    k_gather<<<1024, 256>>>(data, emb);

    // layers i = 3,2,1,0 ; V ping-pong: X -> VA -> VB -> VA -> VB
    int vin = 0;
    for (int it = 0; it < 4; ++it) {
        int layer = 3 - it;
        int vout = (vin == 1) ? 2 : 1;
        k_upart<<<dim3(16, 16), 256>>>(fb2, vin, layer);
        k_ured<<<65, 256>>>();
        k_vupd<<<dim3(64, 16), 128>>>(fb1, vout, layer);
        vin = vout;
    }

    k_fproj<<<dim3(32, 16), 256>>>(Wf, bf, out);
}

// round 12
// speedup vs baseline: 1.1012x; 1.1012x over previous
#include <cuda_runtime.h>
#include <cuda_bf16.h>

// B=16, N_VEC=2048, N_DIM=32, N_W=4, N_HID=128, VOCAB=32000, N_CLASS=10

__device__ __forceinline__ unsigned f2tf32(float x) {
    unsigned r;
    asm("cvt.rna.tf32.f32 %0, %1;" : "=r"(r) : "f"(x));
    return r;
}
__device__ __forceinline__ void mma_tf32(float* c, const unsigned* a, const unsigned* b) {
    asm volatile(
        "mma.sync.aligned.m16n8k8.row.col.f32.tf32.tf32.f32 "
        "{%0,%1,%2,%3}, {%4,%5,%6,%7}, {%8,%9}, {%0,%1,%2,%3};"
        : "+f"(c[0]), "+f"(c[1]), "+f"(c[2]), "+f"(c[3])
        : "r"(a[0]), "r"(a[1]), "r"(a[2]), "r"(a[3]), "r"(b[0]), "r"(b[1]));
}

// ---------- scratch (device globals; allocation is forbidden) ----------
__device__ float g_X [16 * 2048 * 32];
__device__ float g_VA[16 * 2048 * 32];
__device__ float g_VB[16 * 2048 * 32];
__device__ float g_Upart[16 * 16 * 129 * 32];
__device__ float g_U[16 * 129 * 32];
__device__ float g_partF[16 * 32 * 10];
__device__ unsigned g_tick;
__device__ unsigned g_Hh[4 * 16 * 2048 * 128];   // H pre-split hi, [layer][b][r][j]
__device__ unsigned g_Hl[4 * 16 * 2048 * 128];   // H pre-split lo
__device__ unsigned g_Uh[16 * 128 * 32], g_Ul[16 * 128 * 32];

// ---------- X = emb[data], per-block int64/int32 detection ----------
__global__ __launch_bounds__(256) void k_gather(const int* __restrict__ d32,
                                                const float* __restrict__ emb) {
    __shared__ int s_is64;
    int tid = threadIdx.x;
    if (tid == 0) s_is64 = 1;
    __syncthreads();
    if (tid < 32) { if (d32[2 * tid + 1] != 0) s_is64 = 0; }
    __syncthreads();
    int t = blockIdx.x * 256 + tid;
    int row = t >> 3, q = t & 7;
    int idx = s_is64 ? d32[row * 2] : d32[row];
    float4 v = *reinterpret_cast<const float4*>(emb + (size_t)idx * 32 + q * 4);
    *reinterpret_cast<float4*>(g_X + (size_t)row * 32 + q * 4) = v;
}

// ---------- H for ALL layers: H = gelu(X @ fw1 + fb1), pre-split hi/lo ----------
// grid (64 row-tiles, 16 b, 4 layers), 128 threads. GEMM1 identical to proven R10 code.
__global__ __launch_bounds__(128) void k_hall(const float* __restrict__ fw1,
                                              const float* __restrict__ fb1) {
    __shared__ float fb1s[128];
    int layer = blockIdx.z, b = blockIdx.y, n0 = blockIdx.x * 32, tid = threadIdx.x;
    fb1s[tid] = fb1[layer * 128 + tid];
    __syncthreads();

    int w = tid >> 5, lane = tid & 31;
    int grp = lane >> 2, tig = lane & 3;
    int mtb = (w & 1) * 16;
    int ntb = (w >> 1) * 8;

    float c1M[8][4], c1C[8][4];
#pragma unroll
    for (int nt = 0; nt < 8; ++nt)
#pragma unroll
        for (int i = 0; i < 4; ++i) { c1M[nt][i] = 0.f; c1C[nt][i] = 0.f; }

    const float* X0 = g_X + ((size_t)(b * 2048 + n0 + mtb + grp)) * 32;
    const float* X8 = X0 + 8 * 32;
    const float* W = fw1 + (size_t)layer * 4096;
#pragma unroll
    for (int ks = 0; ks < 4; ++ks) {
        int k0 = 8 * ks + tig;
        float x0 = X0[k0], x1 = X8[k0], x2 = X0[k0 + 4], x3 = X8[k0 + 4];
        unsigned ah[4], al[4];
        ah[0] = f2tf32(x0); al[0] = f2tf32(x0 - __uint_as_float(ah[0]));
        ah[1] = f2tf32(x1); al[1] = f2tf32(x1 - __uint_as_float(ah[1]));
        ah[2] = f2tf32(x2); al[2] = f2tf32(x2 - __uint_as_float(ah[2]));
        ah[3] = f2tf32(x3); al[3] = f2tf32(x3 - __uint_as_float(ah[3]));
        const float* Wr0 = W + (size_t)k0 * 128;
        const float* Wr4 = W + (size_t)(k0 + 4) * 128;
#pragma unroll
        for (int nt = 0; nt < 8; ++nt) {
            int j = (ntb + nt) * 8 + grp;
            float b0 = Wr0[j], b1 = Wr4[j];
            unsigned bh[2], bl[2];
            bh[0] = f2tf32(b0); bl[0] = f2tf32(b0 - __uint_as_float(bh[0]));
            bh[1] = f2tf32(b1); bl[1] = f2tf32(b1 - __uint_as_float(bh[1]));
            mma_tf32(c1M[nt], ah, bh);
            mma_tf32(c1C[nt], al, bh);
            mma_tf32(c1C[nt], ah, bl);
        }
    }

    size_t hbase = ((size_t)(layer * 16 + b)) * 2048 * 128;
#pragma unroll
    for (int nt = 0; nt < 8; ++nt) {
        int j0 = (ntb + nt) * 8 + tig * 2;
        float bj0 = fb1s[j0], bj1 = fb1s[j0 + 1];
#pragma unroll
        for (int hf = 0; hf < 2; ++hf) {
            int r = n0 + mtb + grp + hf * 8;
            float v0 = c1M[nt][hf * 2] + c1C[nt][hf * 2] + bj0;
            float v1 = c1M[nt][hf * 2 + 1] + c1C[nt][hf * 2 + 1] + bj1;
            float h0 = 0.5f * v0 * (1.0f + erff(v0 * 0.70710678118654752f));
            float h1 = 0.5f * v1 * (1.0f + erff(v1 * 0.70710678118654752f));
            unsigned hh0 = f2tf32(h0), hh1 = f2tf32(h1);
            unsigned lo0 = f2tf32(h0 - __uint_as_float(hh0));
            unsigned lo1 = f2tf32(h1 - __uint_as_float(hh1));
            *reinterpret_cast<uint2*>(g_Hh + hbase + (size_t)r * 128 + j0) = make_uint2(hh0, hh1);
            *reinterpret_cast<uint2*>(g_Hl + hbase + (size_t)r * 128 + j0) = make_uint2(lo0, lo1);
        }
    }
}

// ---------- U partials via TF32 tensor cores (in-kernel conversion, proven R9) ----------
__global__ __launch_bounds__(256) void k_upart(const float* __restrict__ fw2,
                                               const float* __restrict__ fb2,
                                               int vin_sel, int layer) {
    __shared__ unsigned Bh[128 * 40];
    __shared__ unsigned Bl[128 * 40];
    __shared__ float   Sfb[128];
    int b = blockIdx.y, ch = blockIdx.x, tid = threadIdx.x;
    int m0 = ch * 128;
    const float* Vin = (vin_sel == 0) ? g_X : (vin_sel == 1 ? g_VA : g_VB);
    const float4* vg4 = reinterpret_cast<const float4*>(Vin + ((size_t)(b * 2048 + m0)) * 32);

#pragma unroll
    for (int it = 0; it < 4; ++it) {
        int t4 = tid + it * 256;
        int m = t4 >> 3, dq = (t4 & 7) * 4;
        float4 v = vg4[t4];
        unsigned* ph = Bh + m * 40 + dq;
        unsigned* pl = Bl + m * 40 + dq;
        unsigned h;
        h = f2tf32(v.x); ph[0] = h; pl[0] = f2tf32(v.x - __uint_as_float(h));
        h = f2tf32(v.y); ph[1] = h; pl[1] = f2tf32(v.y - __uint_as_float(h));
        h = f2tf32(v.z); ph[2] = h; pl[2] = f2tf32(v.z - __uint_as_float(h));
        h = f2tf32(v.w); ph[3] = h; pl[3] = f2tf32(v.w - __uint_as_float(h));
    }
    if (tid < 128) Sfb[tid] = fb2[(size_t)layer * 2048 + m0 + tid];
    __syncthreads();

    int w = tid >> 5, lane = tid & 31;
    int grp = lane >> 2, tig = lane & 3;
    const float* A0 = fw2 + ((size_t)(layer * 128 + w * 16 + grp)) * 2048 + m0;
    const float* A8 = A0 + (size_t)8 * 2048;

    float accM[4][4], accC[4][4];
#pragma unroll
    for (int nt = 0; nt < 4; ++nt)
#pragma unroll
        for (int i = 0; i < 4; ++i) { accM[nt][i] = 0.f; accC[nt][i] = 0.f; }

#pragma unroll 4
    for (int ks = 0; ks < 16; ++ks) {
        int c0 = ks * 8 + tig;
        float a0f = A0[c0], a1f = A8[c0], a2f = A0[c0 + 4], a3f = A8[c0 + 4];
        unsigned ah[4], al[4];
        ah[0] = f2tf32(a0f); al[0] = f2tf32(a0f - __uint_as_float(ah[0]));
        ah[1] = f2tf32(a1f); al[1] = f2tf32(a1f - __uint_as_float(ah[1]));
        ah[2] = f2tf32(a2f); al[2] = f2tf32(a2f - __uint_as_float(ah[2]));
        ah[3] = f2tf32(a3f); al[3] = f2tf32(a3f - __uint_as_float(ah[3]));
        const unsigned* rh0 = Bh + (ks * 8 + tig) * 40 + grp;
        const unsigned* rh4 = rh0 + 4 * 40;
        const unsigned* rl0 = Bl + (ks * 8 + tig) * 40 + grp;
        const unsigned* rl4 = rl0 + 4 * 40;
#pragma unroll
        for (int nt = 0; nt < 4; ++nt) {
            unsigned bh[2] = { rh0[nt * 8], rh4[nt * 8] };
            unsigned bl[2] = { rl0[nt * 8], rl4[nt * 8] };
            mma_tf32(accM[nt], ah, bh);
            mma_tf32(accC[nt], al, bh);
            mma_tf32(accC[nt], ah, bl);
        }
    }

    float* up = g_Upart + (((size_t)(b * 16 + ch)) * 129 + w * 16) * 32;
#pragma unroll
    for (int nt = 0; nt < 4; ++nt) {
        int d = nt * 8 + tig * 2;
        float2 r0 = make_float2(accM[nt][0] + accC[nt][0], accM[nt][1] + accC[nt][1]);
        float2 r1 = make_float2(accM[nt][2] + accC[nt][2], accM[nt][3] + accC[nt][3]);
        *reinterpret_cast<float2*>(up + grp * 32 + d) = r0;
        *reinterpret_cast<float2*>(up + (grp + 8) * 32 + d) = r1;
    }

    if (w == 0) {
        float acc = 0.f;
#pragma unroll 8
        for (int m = 0; m < 128; ++m)
            acc += Sfb[m] * (__uint_as_float(Bh[m * 40 + lane]) +
                             __uint_as_float(Bl[m * 40 + lane]));
        g_Upart[(((size_t)(b * 16 + ch)) * 129 + 128) * 32 + lane] = acc;
    }
}

// ---------- reduce split-K partials (+ tf32 split of U; proven R11) ----------
__global__ __launch_bounds__(256) void k_ured() {
    int idx = blockIdx.x * 256 + threadIdx.x;
    if (idx >= 16 * 1032) return;
    int b = idx / 1032, r4 = idx - b * 1032;
    const float4* base = reinterpret_cast<const float4*>(g_Upart) + (size_t)b * 16 * 1032 + r4;
    float4 s = make_float4(0.f, 0.f, 0.f, 0.f);
#pragma unroll
    for (int c = 0; c < 16; ++c) {
        float4 v = base[(size_t)c * 1032];
        s.x += v.x; s.y += v.y; s.z += v.z; s.w += v.w;
    }
    reinterpret_cast<float4*>(g_U)[(size_t)b * 1032 + r4] = s;
    if (r4 < 1024) {
        uint4 h, l;
        h.x = f2tf32(s.x); l.x = f2tf32(s.x - __uint_as_float(h.x));
        h.y = f2tf32(s.y); l.y = f2tf32(s.y - __uint_as_float(h.y));
        h.z = f2tf32(s.z); l.z = f2tf32(s.z - __uint_as_float(h.z));
        h.w = f2tf32(s.w); l.w = f2tf32(s.w - __uint_as_float(h.w));
        reinterpret_cast<uint4*>(g_Uh)[(size_t)b * 1024 + r4] = h;
        reinterpret_cast<uint4*>(g_Ul)[(size_t)b * 1024 + r4] = l;
    }
}

// ---------- vupd2: V' = H @ U + crow  (GEMM2 only; H staged coalesced) ----------
// 32 rows/block, 128 threads, grid (64,16). smem 33.8KB.
__global__ __launch_bounds__(128) void k_vupd2(int vout_sel, int layer) {
    __shared__ unsigned Hh[32 * 132], Hl[32 * 132];
    __shared__ float crow[32];
    int b = blockIdx.y, n0 = blockIdx.x * 32, tid = threadIdx.x;

    // stage H tile (rows n0..n0+31) hi/lo via coalesced uint4 loads
    size_t hbase = ((size_t)(layer * 16 + b)) * 2048 * 128 + (size_t)n0 * 128;
    const uint4* Hg4h = reinterpret_cast<const uint4*>(g_Hh + hbase);
    const uint4* Hg4l = reinterpret_cast<const uint4*>(g_Hl + hbase);
#pragma unroll
    for (int it = 0; it < 8; ++it) {
        int t4 = tid + it * 128;                 // 1024 uint4 = 32r x 32(q4)
        int r = t4 >> 5, q = (t4 & 31) * 4;
        *reinterpret_cast<uint4*>(Hh + r * 132 + q) = Hg4h[t4];
        *reinterpret_cast<uint4*>(Hl + r * 132 + q) = Hg4l[t4];
    }
    if (tid < 32) crow[tid] = g_U[(size_t)b * 4128 + 4096 + tid];
    __syncthreads();

    int w = tid >> 5, lane = tid & 31;
    int grp = lane >> 2, tig = lane & 3;
    int mtb = (w & 1) * 16;
    int ntb2 = (w >> 1) * 2;

    float c2M[2][4], c2C[2][4];
#pragma unroll
    for (int nt = 0; nt < 2; ++nt)
#pragma unroll
        for (int i = 0; i < 4; ++i) { c2M[nt][i] = 0.f; c2C[nt][i] = 0.f; }

    int ra = (mtb + grp) * 132;
    int rb = ra + 8 * 132;
    const unsigned* Ubh = g_Uh + (size_t)b * 4096;
    const unsigned* Ubl = g_Ul + (size_t)b * 4096;
#pragma unroll 4
    for (int ks = 0; ks < 16; ++ks) {
        int k0 = 8 * ks + tig;
        unsigned ah[4] = { Hh[ra + k0], Hh[rb + k0], Hh[ra + k0 + 4], Hh[rb + k0 + 4] };
        unsigned al[4] = { Hl[ra + k0], Hl[rb + k0], Hl[ra + k0 + 4], Hl[rb + k0 + 4] };
#pragma unroll
        for (int nt = 0; nt < 2; ++nt) {
            int n = (ntb2 + nt) * 8 + grp;
            unsigned bh[2] = { Ubh[k0 * 32 + n], Ubh[(k0 + 4) * 32 + n] };
            unsigned bl[2] = { Ubl[k0 * 32 + n], Ubl[(k0 + 4) * 32 + n] };
            mma_tf32(c2M[nt], ah, bh);
            mma_tf32(c2C[nt], al, bh);
            mma_tf32(c2C[nt], ah, bl);
        }
    }

    float* Vout = (vout_sel == 1) ? g_VA : g_VB;
#pragma unroll
    for (int nt = 0; nt < 2; ++nt) {
        int d0 = (ntb2 + nt) * 8 + tig * 2;
        float cc0 = crow[d0], cc1 = crow[d0 + 1];
#pragma unroll
        for (int hf = 0; hf < 2; ++hf) {
            int r = n0 + mtb + grp + hf * 8;
            float2 o = make_float2(c2M[nt][hf * 2] + c2C[nt][hf * 2] + cc0,
                                   c2M[nt][hf * 2 + 1] + c2C[nt][hf * 2 + 1] + cc1);
            *reinterpret_cast<float2*>(Vout + ((size_t)(b * 2048 + r)) * 32 + d0) = o;
        }
    }
}

// ---------- final projection, fused partial + completion (ticket) ----------
__global__ __launch_bounds__(256) void k_fproj(const float* __restrict__ Wf,
                                               const float* __restrict__ bf,
                                               float* __restrict__ out) {
    __shared__ float wsum[8][10];
    __shared__ int s_last;
    int b = blockIdx.y, ch = blockIdx.x, tid = threadIdx.x;
    int lane = tid & 31, w = tid >> 5;
    float acc[10];
#pragma unroll
    for (int c = 0; c < 10; ++c) acc[c] = 0.f;
    const float* Vb = g_VB + (size_t)b * 65536 + ch * 2048;
#pragma unroll
    for (int q = 0; q < 8; ++q) {
        int k = q * 256 + tid;
        float v = Vb[k];
        const float* wr = Wf + (size_t)(ch * 2048 + k) * 10;
#pragma unroll
        for (int c = 0; c < 10; ++c) acc[c] += v * wr[c];
    }
#pragma unroll
    for (int c = 0; c < 10; ++c) {
#pragma unroll
        for (int s = 16; s > 0; s >>= 1) acc[c] += __shfl_down_sync(0xffffffffu, acc[c], s);
        if (lane == 0) wsum[w][c] = acc[c];
    }
    __syncthreads();
    if (tid < 10) {
        float s = 0.f;
#pragma unroll
        for (int ww = 0; ww < 8; ++ww) s += wsum[ww][tid];
        g_partF[((size_t)(b * 32 + ch)) * 10 + tid] = s;
    }
    __threadfence();
    __syncthreads();
    if (tid == 0) {
        unsigned prev = atomicAdd(&g_tick, 1u);
        s_last = (prev == 511u) ? 1 : 0;
    }
    __syncthreads();
    if (s_last) {
        __threadfence();
        if (tid < 160) {
            int bb = tid / 10, c = tid % 10;
            float s = bf[c];
#pragma unroll
            for (int cc = 0; cc < 32; ++cc) s += g_partF[((size_t)(bb * 32 + cc)) * 10 + c];
            out[tid] = s;
        }
        if (tid == 0) g_tick = 0u;
    }
}

extern "C" void kernel_launch(void* const* d_in, const int* in_sizes, int n_in,
                              void* d_out, int out_size) {
    const int*   data = (const int*)  d_in[0];
    const float* emb  = (const float*)d_in[1];
    const float* fw1  = (const float*)d_in[2];
    const float* fb1  = (const float*)d_in[3];
    const float* fw2  = (const float*)d_in[4];
    const float* fb2  = (const float*)d_in[5];
    const float* Wf   = (const float*)d_in[6];
    const float* bf   = (const float*)d_in[7];
    float* out = (float*)d_out;

    k_gather<<<1024, 256>>>(data, emb);
    k_hall<<<dim3(64, 16, 4), 128>>>(fw1, fb1);   // all layers' H, once

    // layers i = 3,2,1,0 ; V ping-pong: X -> VA -> VB -> VA -> VB
    int vin = 0;
    for (int it = 0; it < 4; ++it) {
        int layer = 3 - it;
        int vout = (vin == 1) ? 2 : 1;
        k_upart<<<dim3(16, 16), 256>>>(fw2, fb2, vin, layer);
        k_ured<<<65, 256>>>();
        k_vupd2<<<dim3(64, 16), 128>>>(vout, layer);
        vin = vout;
    }

    k_fproj<<<dim3(32, 16), 256>>>(Wf, bf, out);
}

// round 13
// speedup vs baseline: 1.1265x; 1.0230x over previous
#include <cuda_runtime.h>
#include <cuda_bf16.h>

// B=16, N_VEC=2048, N_DIM=32, N_W=4, N_HID=128, VOCAB=32000, N_CLASS=10

__device__ __forceinline__ unsigned f2tf32(float x) {
    unsigned r;
    asm("cvt.rna.tf32.f32 %0, %1;" : "=r"(r) : "f"(x));
    return r;
}
__device__ __forceinline__ void mma_tf32(float* c, const unsigned* a, const unsigned* b) {
    asm volatile(
        "mma.sync.aligned.m16n8k8.row.col.f32.tf32.tf32.f32 "
        "{%0,%1,%2,%3}, {%4,%5,%6,%7}, {%8,%9}, {%0,%1,%2,%3};"
        : "+f"(c[0]), "+f"(c[1]), "+f"(c[2]), "+f"(c[3])
        : "r"(a[0]), "r"(a[1]), "r"(a[2]), "r"(a[3]), "r"(b[0]), "r"(b[1]));
}

// ---------- scratch (device globals; allocation is forbidden) ----------
__device__ float g_X [16 * 2048 * 32];
__device__ float g_VA[16 * 2048 * 32];
__device__ float g_VB[16 * 2048 * 32];
__device__ float g_Upart[16 * 16 * 129 * 32];
__device__ float g_U[16 * 129 * 32];
__device__ float g_partF[16 * 32 * 10];
__device__ unsigned g_tick;
__device__ unsigned g_fw1h[4 * 32 * 128], g_fw1l[4 * 32 * 128];   // small, L1/L2-hot
__device__ unsigned g_Uh[16 * 128 * 32],  g_Ul[16 * 128 * 32];

// ---------- one-shot fw1 split (tiny) ----------
__global__ __launch_bounds__(256) void k_wsplit1(const float* __restrict__ fw1) {
    int idx = blockIdx.x * 256 + threadIdx.x;    // 16384 elements
    float v = fw1[idx];
    unsigned h = f2tf32(v);
    g_fw1h[idx] = h;
    g_fw1l[idx] = f2tf32(v - __uint_as_float(h));
}

// ---------- X = emb[data], per-block int64/int32 detection ----------
__global__ __launch_bounds__(256) void k_gather(const int* __restrict__ d32,
                                                const float* __restrict__ emb) {
    __shared__ int s_is64;
    int tid = threadIdx.x;
    if (tid == 0) s_is64 = 1;
    __syncthreads();
    if (tid < 32) { if (d32[2 * tid + 1] != 0) s_is64 = 0; }
    __syncthreads();
    int t = blockIdx.x * 256 + tid;
    int row = t >> 3, q = t & 7;
    int idx = s_is64 ? d32[row * 2] : d32[row];
    float4 v = *reinterpret_cast<const float4*>(emb + (size_t)idx * 32 + q * 4);
    *reinterpret_cast<float4*>(g_X + (size_t)row * 32 + q * 4) = v;
}

// ---------- U partials via TF32 tensor cores (proven R9, byte-identical) ----------
__global__ __launch_bounds__(256) void k_upart(const float* __restrict__ fw2,
                                               const float* __restrict__ fb2,
                                               int vin_sel, int layer) {
    __shared__ unsigned Bh[128 * 40];
    __shared__ unsigned Bl[128 * 40];
    __shared__ float   Sfb[128];
    int b = blockIdx.y, ch = blockIdx.x, tid = threadIdx.x;
    int m0 = ch * 128;
    const float* Vin = (vin_sel == 0) ? g_X : (vin_sel == 1 ? g_VA : g_VB);
    const float4* vg4 = reinterpret_cast<const float4*>(Vin + ((size_t)(b * 2048 + m0)) * 32);

#pragma unroll
    for (int it = 0; it < 4; ++it) {
        int t4 = tid + it * 256;
        int m = t4 >> 3, dq = (t4 & 7) * 4;
        float4 v = vg4[t4];
        unsigned* ph = Bh + m * 40 + dq;
        unsigned* pl = Bl + m * 40 + dq;
        unsigned h;
        h = f2tf32(v.x); ph[0] = h; pl[0] = f2tf32(v.x - __uint_as_float(h));
        h = f2tf32(v.y); ph[1] = h; pl[1] = f2tf32(v.y - __uint_as_float(h));
        h = f2tf32(v.z); ph[2] = h; pl[2] = f2tf32(v.z - __uint_as_float(h));
        h = f2tf32(v.w); ph[3] = h; pl[3] = f2tf32(v.w - __uint_as_float(h));
    }
    if (tid < 128) Sfb[tid] = fb2[(size_t)layer * 2048 + m0 + tid];
    __syncthreads();

    int w = tid >> 5, lane = tid & 31;
    int grp = lane >> 2, tig = lane & 3;
    const float* A0 = fw2 + ((size_t)(layer * 128 + w * 16 + grp)) * 2048 + m0;
    const float* A8 = A0 + (size_t)8 * 2048;

    float accM[4][4], accC[4][4];
#pragma unroll
    for (int nt = 0; nt < 4; ++nt)
#pragma unroll
        for (int i = 0; i < 4; ++i) { accM[nt][i] = 0.f; accC[nt][i] = 0.f; }

#pragma unroll 4
    for (int ks = 0; ks < 16; ++ks) {
        int c0 = ks * 8 + tig;
        float a0f = A0[c0], a1f = A8[c0], a2f = A0[c0 + 4], a3f = A8[c0 + 4];
        unsigned ah[4], al[4];
        ah[0] = f2tf32(a0f); al[0] = f2tf32(a0f - __uint_as_float(ah[0]));
        ah[1] = f2tf32(a1f); al[1] = f2tf32(a1f - __uint_as_float(ah[1]));
        ah[2] = f2tf32(a2f); al[2] = f2tf32(a2f - __uint_as_float(ah[2]));
        ah[3] = f2tf32(a3f); al[3] = f2tf32(a3f - __uint_as_float(ah[3]));
        const unsigned* rh0 = Bh + (ks * 8 + tig) * 40 + grp;
        const unsigned* rh4 = rh0 + 4 * 40;
        const unsigned* rl0 = Bl + (ks * 8 + tig) * 40 + grp;
        const unsigned* rl4 = rl0 + 4 * 40;
#pragma unroll
        for (int nt = 0; nt < 4; ++nt) {
            unsigned bh[2] = { rh0[nt * 8], rh4[nt * 8] };
            unsigned bl[2] = { rl0[nt * 8], rl4[nt * 8] };
            mma_tf32(accM[nt], ah, bh);
            mma_tf32(accC[nt], al, bh);
            mma_tf32(accC[nt], ah, bl);
        }
    }

    float* up = g_Upart + (((size_t)(b * 16 + ch)) * 129 + w * 16) * 32;
#pragma unroll
    for (int nt = 0; nt < 4; ++nt) {
        int d = nt * 8 + tig * 2;
        float2 r0 = make_float2(accM[nt][0] + accC[nt][0], accM[nt][1] + accC[nt][1]);
        float2 r1 = make_float2(accM[nt][2] + accC[nt][2], accM[nt][3] + accC[nt][3]);
        *reinterpret_cast<float2*>(up + grp * 32 + d) = r0;
        *reinterpret_cast<float2*>(up + (grp + 8) * 32 + d) = r1;
    }

    if (w == 0) {
        float acc = 0.f;
#pragma unroll 8
        for (int m = 0; m < 128; ++m)
            acc += Sfb[m] * (__uint_as_float(Bh[m * 40 + lane]) +
                             __uint_as_float(Bl[m * 40 + lane]));
        g_Upart[(((size_t)(b * 16 + ch)) * 129 + 128) * 32 + lane] = acc;
    }
}

// ---------- reduce split-K partials (+ tf32 split of U; proven R11) ----------
__global__ __launch_bounds__(256) void k_ured() {
    int idx = blockIdx.x * 256 + threadIdx.x;
    if (idx >= 16 * 1032) return;
    int b = idx / 1032, r4 = idx - b * 1032;
    const float4* base = reinterpret_cast<const float4*>(g_Upart) + (size_t)b * 16 * 1032 + r4;
    float4 s = make_float4(0.f, 0.f, 0.f, 0.f);
#pragma unroll
    for (int c = 0; c < 16; ++c) {
        float4 v = base[(size_t)c * 1032];
        s.x += v.x; s.y += v.y; s.z += v.z; s.w += v.w;
    }
    reinterpret_cast<float4*>(g_U)[(size_t)b * 1032 + r4] = s;
    if (r4 < 1024) {
        uint4 h, l;
        h.x = f2tf32(s.x); l.x = f2tf32(s.x - __uint_as_float(h.x));
        h.y = f2tf32(s.y); l.y = f2tf32(s.y - __uint_as_float(h.y));
        h.z = f2tf32(s.z); l.z = f2tf32(s.z - __uint_as_float(h.z));
        h.w = f2tf32(s.w); l.w = f2tf32(s.w - __uint_as_float(h.w));
        reinterpret_cast<uint4*>(g_Uh)[(size_t)b * 1024 + r4] = h;
        reinterpret_cast<uint4*>(g_Ul)[(size_t)b * 1024 + r4] = l;
    }
}

// ---------- fused tensor-core vupd: pre-split fw1/U from global, X cvt in-register ----
// 32 rows/block, 128 threads (4 warps), grid (64,16). 34.4KB static smem.
__global__ __launch_bounds__(128) void k_vupd(const float* __restrict__ fb1,
                                              int vout_sel, int layer) {
    __shared__ unsigned Hh[32 * 132], Hl[32 * 132];
    __shared__ float crow[32], fb1s[128];
    int b = blockIdx.y, n0 = blockIdx.x * 32, tid = threadIdx.x;

    if (tid < 32) crow[tid] = g_U[(size_t)b * 4128 + 4096 + tid];
    fb1s[tid] = fb1[layer * 128 + tid];
    __syncthreads();

    int w = tid >> 5, lane = tid & 31;
    int grp = lane >> 2, tig = lane & 3;
    int mtb = (w & 1) * 16;
    int ntb = (w >> 1) * 8;

    // ---- GEMM1: C1[32r x 128j] = X @ fw1 ----
    float c1M[8][4], c1C[8][4];
#pragma unroll
    for (int nt = 0; nt < 8; ++nt)
#pragma unroll
        for (int i = 0; i < 4; ++i) { c1M[nt][i] = 0.f; c1C[nt][i] = 0.f; }

    const float* X0 = g_X + ((size_t)(b * 2048 + n0 + mtb + grp)) * 32;
    const float* X8 = X0 + 8 * 32;
    const unsigned* Wh = g_fw1h + (size_t)layer * 4096;
    const unsigned* Wl = g_fw1l + (size_t)layer * 4096;
#pragma unroll
    for (int ks = 0; ks < 4; ++ks) {
        int k0 = 8 * ks + tig;
        float x0 = X0[k0], x1 = X8[k0], x2 = X0[k0 + 4], x3 = X8[k0 + 4];
        unsigned ah[4], al[4];
        ah[0] = f2tf32(x0); al[0] = f2tf32(x0 - __uint_as_float(ah[0]));
        ah[1] = f2tf32(x1); al[1] = f2tf32(x1 - __uint_as_float(ah[1]));
        ah[2] = f2tf32(x2); al[2] = f2tf32(x2 - __uint_as_float(ah[2]));
        ah[3] = f2tf32(x3); al[3] = f2tf32(x3 - __uint_as_float(ah[3]));
        const unsigned* Wr0h = Wh + (size_t)k0 * 128;
        const unsigned* Wr4h = Wh + (size_t)(k0 + 4) * 128;
        const unsigned* Wr0l = Wl + (size_t)k0 * 128;
        const unsigned* Wr4l = Wl + (size_t)(k0 + 4) * 128;
#pragma unroll
        for (int nt = 0; nt < 8; ++nt) {
            int j = (ntb + nt) * 8 + grp;
            unsigned bh[2] = { Wr0h[j], Wr4h[j] };
            unsigned bl[2] = { Wr0l[j], Wr4l[j] };
            mma_tf32(c1M[nt], ah, bh);
            mma_tf32(c1C[nt], al, bh);
            mma_tf32(c1C[nt], ah, bl);
        }
    }

    // ---- bias + exact GELU in-register, write H hi/lo to smem ----
#pragma unroll
    for (int nt = 0; nt < 8; ++nt) {
        int j0 = (ntb + nt) * 8 + tig * 2;
        float bj0 = fb1s[j0], bj1 = fb1s[j0 + 1];
#pragma unroll
        for (int hf = 0; hf < 2; ++hf) {
            int r = mtb + grp + hf * 8;
            float v0 = c1M[nt][hf * 2] + c1C[nt][hf * 2] + bj0;
            float v1 = c1M[nt][hf * 2 + 1] + c1C[nt][hf * 2 + 1] + bj1;
            float h0 = 0.5f * v0 * (1.0f + erff(v0 * 0.70710678118654752f));
            float h1 = 0.5f * v1 * (1.0f + erff(v1 * 0.70710678118654752f));
            unsigned hh0 = f2tf32(h0), hh1 = f2tf32(h1);
            unsigned lo0 = f2tf32(h0 - __uint_as_float(hh0));
            unsigned lo1 = f2tf32(h1 - __uint_as_float(hh1));
            *reinterpret_cast<uint2*>(Hh + r * 132 + j0) = make_uint2(hh0, hh1);
            *reinterpret_cast<uint2*>(Hl + r * 132 + j0) = make_uint2(lo0, lo1);
        }
    }
    __syncthreads();

    // ---- GEMM2: V'[32r x 32d] = H @ U + crow (U pre-split, direct LDG) ----
    int ntb2 = (w >> 1) * 2;
    float c2M[2][4], c2C[2][4];
#pragma unroll
    for (int nt = 0; nt < 2; ++nt)
#pragma unroll
        for (int i = 0; i < 4; ++i) { c2M[nt][i] = 0.f; c2C[nt][i] = 0.f; }

    int ra = (mtb + grp) * 132;
    int rb = ra + 8 * 132;
    const unsigned* Ubh = g_Uh + (size_t)b * 4096;
    const unsigned* Ubl = g_Ul + (size_t)b * 4096;
#pragma unroll 4
    for (int ks = 0; ks < 16; ++ks) {
        int k0 = 8 * ks + tig;
        unsigned ah[4] = { Hh[ra + k0], Hh[rb + k0], Hh[ra + k0 + 4], Hh[rb + k0 + 4] };
        unsigned al[4] = { Hl[ra + k0], Hl[rb + k0], Hl[ra + k0 + 4], Hl[rb + k0 + 4] };
#pragma unroll
        for (int nt = 0; nt < 2; ++nt) {
            int n = (ntb2 + nt) * 8 + grp;
            unsigned bh[2] = { Ubh[k0 * 32 + n], Ubh[(k0 + 4) * 32 + n] };
            unsigned bl[2] = { Ubl[k0 * 32 + n], Ubl[(k0 + 4) * 32 + n] };
            mma_tf32(c2M[nt], ah, bh);
            mma_tf32(c2C[nt], al, bh);
            mma_tf32(c2C[nt], ah, bl);
        }
    }

    float* Vout = (vout_sel == 1) ? g_VA : g_VB;
#pragma unroll
    for (int nt = 0; nt < 2; ++nt) {
        int d0 = (ntb2 + nt) * 8 + tig * 2;
        float cc0 = crow[d0], cc1 = crow[d0 + 1];
#pragma unroll
        for (int hf = 0; hf < 2; ++hf) {
            int r = n0 + mtb + grp + hf * 8;
            float2 o = make_float2(c2M[nt][hf * 2] + c2C[nt][hf * 2] + cc0,
                                   c2M[nt][hf * 2 + 1] + c2C[nt][hf * 2 + 1] + cc1);
            *reinterpret_cast<float2*>(Vout + ((size_t)(b * 2048 + r)) * 32 + d0) = o;
        }
    }
}

// ---------- final projection, fused partial + completion (ticket) ----------
__global__ __launch_bounds__(256) void k_fproj(const float* __restrict__ Wf,
                                               const float* __restrict__ bf,
                                               float* __restrict__ out) {
    __shared__ float wsum[8][10];
    __shared__ int s_last;
    int b = blockIdx.y, ch = blockIdx.x, tid = threadIdx.x;
    int lane = tid & 31, w = tid >> 5;
    float acc[10];
#pragma unroll
    for (int c = 0; c < 10; ++c) acc[c] = 0.f;
    const float* Vb = g_VB + (size_t)b * 65536 + ch * 2048;
#pragma unroll
    for (int q = 0; q < 8; ++q) {
        int k = q * 256 + tid;
        float v = Vb[k];
        const float* wr = Wf + (size_t)(ch * 2048 + k) * 10;
#pragma unroll
        for (int c = 0; c < 10; ++c) acc[c] += v * wr[c];
    }
#pragma unroll
    for (int c = 0; c < 10; ++c) {
#pragma unroll
        for (int s = 16; s > 0; s >>= 1) acc[c] += __shfl_down_sync(0xffffffffu, acc[c], s);
        if (lane == 0) wsum[w][c] = acc[c];
    }
    __syncthreads();
    if (tid < 10) {
        float s = 0.f;
#pragma unroll
        for (int ww = 0; ww < 8; ++ww) s += wsum[ww][tid];
        g_partF[((size_t)(b * 32 + ch)) * 10 + tid] = s;
    }
    __threadfence();
    __syncthreads();
    if (tid == 0) {
        unsigned prev = atomicAdd(&g_tick, 1u);
        s_last = (prev == 511u) ? 1 : 0;
    }
    __syncthreads();
    if (s_last) {
        __threadfence();
        if (tid < 160) {
            int bb = tid / 10, c = tid % 10;
            float s = bf[c];
#pragma unroll
            for (int cc = 0; cc < 32; ++cc) s += g_partF[((size_t)(bb * 32 + cc)) * 10 + c];
            out[tid] = s;
        }
        if (tid == 0) g_tick = 0u;
    }
}

extern "C" void kernel_launch(void* const* d_in, const int* in_sizes, int n_in,
                              void* d_out, int out_size) {
    const int*   data = (const int*)  d_in[0];
    const float* emb  = (const float*)d_in[1];
    const float* fw1  = (const float*)d_in[2];
    const float* fb1  = (const float*)d_in[3];
    const float* fw2  = (const float*)d_in[4];
    const float* fb2  = (const float*)d_in[5];
    const float* Wf   = (const float*)d_in[6];
    const float* bf   = (const float*)d_in[7];
    float* out = (float*)d_out;

    k_wsplit1<<<64, 256>>>(fw1);
    k_gather<<<1024, 256>>>(data, emb);

    // layers i = 3,2,1,0 ; V ping-pong: X -> VA -> VB -> VA -> VB
    int vin = 0;
    for (int it = 0; it < 4; ++it) {
        int layer = 3 - it;
        int vout = (vin == 1) ? 2 : 1;
        k_upart<<<dim3(16, 16), 256>>>(fw2, fb2, vin, layer);
        k_ured<<<65, 256>>>();
        k_vupd<<<dim3(64, 16), 128>>>(fb1, vout, layer);
        vin = vout;
    }

    k_fproj<<<dim3(32, 16), 256>>>(Wf, bf, out);
}

// round 14
// speedup vs baseline: 1.4372x; 1.2758x over previous
#include <cuda_runtime.h>
#include <cuda_bf16.h>

// B=16, N_VEC=2048, N_DIM=32, N_W=4, N_HID=128, VOCAB=32000, N_CLASS=10

typedef unsigned long long u64;

__device__ __forceinline__ u64 fma2(u64 a, u64 b, u64 c) {
    u64 d;
    asm("fma.rn.f32x2 %0, %1, %2, %3;" : "=l"(d) : "l"(a), "l"(b), "l"(c));
    return d;
}
__device__ __forceinline__ u64 pack2(float lo, float hi) {
    u64 r;
    asm("mov.b64 %0, {%1, %2};" : "=l"(r) : "f"(lo), "f"(hi));
    return r;
}
__device__ __forceinline__ float2 unpack2(u64 v) {
    float2 f;
    asm("mov.b64 {%0, %1}, %2;" : "=f"(f.x), "=f"(f.y) : "l"(v));
    return f;
}
__device__ __forceinline__ unsigned f2tf32(float x) {
    unsigned r;
    asm("cvt.rna.tf32.f32 %0, %1;" : "=r"(r) : "f"(x));
    return r;
}
__device__ __forceinline__ void mma_tf32(float* c, const unsigned* a, const unsigned* b) {
    asm volatile(
        "mma.sync.aligned.m16n8k8.row.col.f32.tf32.tf32.f32 "
        "{%0,%1,%2,%3}, {%4,%5,%6,%7}, {%8,%9}, {%0,%1,%2,%3};"
        : "+f"(c[0]), "+f"(c[1]), "+f"(c[2]), "+f"(c[3])
        : "r"(a[0]), "r"(a[1]), "r"(a[2]), "r"(a[3]), "r"(b[0]), "r"(b[1]));
}

// ---------- scratch (device globals; allocation is forbidden) ----------
__device__ float g_X [16 * 2048 * 32];
__device__ float g_VA[16 * 2048 * 32];
__device__ float g_VB[16 * 2048 * 32];
__device__ float g_Upart[16 * 16 * 129 * 32];   // [b][chunk(16)][129][32] (row 128 = bias c)
__device__ float g_U[16 * 129 * 32];            // [b][129][32]
__device__ float g_partF[16 * 32 * 10];
__device__ unsigned g_tick;

// ---------- X = emb[data], with per-block int64/int32 detection ----------
__global__ __launch_bounds__(256) void k_gather(const int* __restrict__ d32,
                                                const float* __restrict__ emb) {
    __shared__ int s_is64;
    int tid = threadIdx.x;
    if (tid == 0) s_is64 = 1;
    __syncthreads();
    if (tid < 32) { if (d32[2 * tid + 1] != 0) s_is64 = 0; }
    __syncthreads();
    int t = blockIdx.x * 256 + tid;
    int row = t >> 3, q = t & 7;
    int idx = s_is64 ? d32[row * 2] : d32[row];
    float4 v = *reinterpret_cast<const float4*>(emb + (size_t)idx * 32 + q * 4);
    *reinterpret_cast<float4*>(g_X + (size_t)row * 32 + q * 4) = v;
}

// ---------- U partials via TF32 tensor cores (3xTF32; byte-identical R9) ----------
__global__ __launch_bounds__(256) void k_upart(const float* __restrict__ fw2,
                                               const float* __restrict__ fb2,
                                               int vin_sel, int layer) {
    __shared__ unsigned Bh[128 * 40];
    __shared__ unsigned Bl[128 * 40];
    __shared__ float   Sfb[128];
    int b = blockIdx.y, ch = blockIdx.x, tid = threadIdx.x;
    int m0 = ch * 128;
    const float* Vin = (vin_sel == 0) ? g_X : (vin_sel == 1 ? g_VA : g_VB);
    const float4* vg4 = reinterpret_cast<const float4*>(Vin + ((size_t)(b * 2048 + m0)) * 32);

#pragma unroll
    for (int it = 0; it < 4; ++it) {
        int t4 = tid + it * 256;
        int m = t4 >> 3, dq = (t4 & 7) * 4;
        float4 v = vg4[t4];
        unsigned* ph = Bh + m * 40 + dq;
        unsigned* pl = Bl + m * 40 + dq;
        unsigned h;
        h = f2tf32(v.x); ph[0] = h; pl[0] = f2tf32(v.x - __uint_as_float(h));
        h = f2tf32(v.y); ph[1] = h; pl[1] = f2tf32(v.y - __uint_as_float(h));
        h = f2tf32(v.z); ph[2] = h; pl[2] = f2tf32(v.z - __uint_as_float(h));
        h = f2tf32(v.w); ph[3] = h; pl[3] = f2tf32(v.w - __uint_as_float(h));
    }
    if (tid < 128) Sfb[tid] = fb2[(size_t)layer * 2048 + m0 + tid];
    __syncthreads();

    int w = tid >> 5, lane = tid & 31;
    int grp = lane >> 2, tig = lane & 3;
    const float* A0 = fw2 + ((size_t)(layer * 128 + w * 16 + grp)) * 2048 + m0;
    const float* A8 = A0 + (size_t)8 * 2048;

    float accM[4][4], accC[4][4];
#pragma unroll
    for (int nt = 0; nt < 4; ++nt)
#pragma unroll
        for (int i = 0; i < 4; ++i) { accM[nt][i] = 0.f; accC[nt][i] = 0.f; }

#pragma unroll 4
    for (int ks = 0; ks < 16; ++ks) {
        int c0 = ks * 8 + tig;
        float a0f = A0[c0], a1f = A8[c0], a2f = A0[c0 + 4], a3f = A8[c0 + 4];
        unsigned ah[4], al[4];
        ah[0] = f2tf32(a0f); al[0] = f2tf32(a0f - __uint_as_float(ah[0]));
        ah[1] = f2tf32(a1f); al[1] = f2tf32(a1f - __uint_as_float(ah[1]));
        ah[2] = f2tf32(a2f); al[2] = f2tf32(a2f - __uint_as_float(ah[2]));
        ah[3] = f2tf32(a3f); al[3] = f2tf32(a3f - __uint_as_float(ah[3]));
        const unsigned* rh0 = Bh + (ks * 8 + tig) * 40 + grp;
        const unsigned* rh4 = rh0 + 4 * 40;
        const unsigned* rl0 = Bl + (ks * 8 + tig) * 40 + grp;
        const unsigned* rl4 = rl0 + 4 * 40;
#pragma unroll
        for (int nt = 0; nt < 4; ++nt) {
            unsigned bh[2] = { rh0[nt * 8], rh4[nt * 8] };
            unsigned bl[2] = { rl0[nt * 8], rl4[nt * 8] };
            mma_tf32(accM[nt], ah, bh);
            mma_tf32(accC[nt], al, bh);
            mma_tf32(accC[nt], ah, bl);
        }
    }

    float* up = g_Upart + (((size_t)(b * 16 + ch)) * 129 + w * 16) * 32;
#pragma unroll
    for (int nt = 0; nt < 4; ++nt) {
        int d = nt * 8 + tig * 2;
        float2 r0 = make_float2(accM[nt][0] + accC[nt][0], accM[nt][1] + accC[nt][1]);
        float2 r1 = make_float2(accM[nt][2] + accC[nt][2], accM[nt][3] + accC[nt][3]);
        *reinterpret_cast<float2*>(up + grp * 32 + d) = r0;
        *reinterpret_cast<float2*>(up + (grp + 8) * 32 + d) = r1;
    }

    if (w == 0) {
        float acc = 0.f;
#pragma unroll 8
        for (int m = 0; m < 128; ++m)
            acc += Sfb[m] * (__uint_as_float(Bh[m * 40 + lane]) +
                             __uint_as_float(Bl[m * 40 + lane]));
        g_Upart[(((size_t)(b * 16 + ch)) * 129 + 128) * 32 + lane] = acc;
    }
}

// ---------- reduce split-K partials: 2 threads per output, halved latency chain ----
// grid 129 x 512 threads: tid<256 -> chunks 0-7, tid>=256 -> chunks 8-15, combine via smem.
__global__ __launch_bounds__(512) void k_ured() {
    __shared__ float4 s_half[256];
    int tid = threadIdx.x;
    int o = blockIdx.x * 256 + (tid & 255);      // 129*256 >= 16512 outputs
    int half = tid >> 8;
    bool valid = (o < 16512);
    float4 s = make_float4(0.f, 0.f, 0.f, 0.f);
    if (valid) {
        int b = o / 1032, r4 = o - b * 1032;
        const float4* base = reinterpret_cast<const float4*>(g_Upart)
                           + (size_t)b * 16 * 1032 + (size_t)half * 8 * 1032 + r4;
#pragma unroll
        for (int c = 0; c < 8; ++c) {
            float4 v = base[(size_t)c * 1032];
            s.x += v.x; s.y += v.y; s.z += v.z; s.w += v.w;
        }
    }
    if (half) s_half[tid & 255] = s;
    __syncthreads();
    if (!half && valid) {
        float4 t = s_half[tid];
        s.x += t.x; s.y += t.y; s.z += t.z; s.w += t.w;
        int b = o / 1032, r4 = o - b * 1032;
        reinterpret_cast<float4*>(g_U)[(size_t)b * 1032 + r4] = s;
    }
}

// ---------- fused: H = gelu(X @ fw1 + fb1); V' = H @ U + c (byte-identical R9) ----------
__global__ __launch_bounds__(128) void k_vupd(const float* __restrict__ fw1,
                                              const float* __restrict__ fb1,
                                              int vout_sel, int layer) {
    __shared__ __align__(16) float Xs[32 * 32];
    __shared__ __align__(16) float Us[129 * 32];
    __shared__ __align__(16) float HsT[128 * 34];
    int b = blockIdx.y, n0 = blockIdx.x * 32, tid = threadIdx.x;

    const float* xg = g_X + ((size_t)(b * 2048 + n0)) * 32;
#pragma unroll
    for (int it = 0; it < 8; ++it) Xs[tid + it * 128] = xg[tid + it * 128];
    const float* Ug = g_U + (size_t)b * 4128;
#pragma unroll
    for (int it = 0; it < 32; ++it) Us[tid + it * 128] = Ug[tid + it * 128];
    if (tid < 32) Us[4096 + tid] = Ug[4096 + tid];
    __syncthreads();

    {
        int jA = (tid & 63) * 2, jB = jA + 1;
        int half = tid >> 6;
        const float* wbase = fw1 + (size_t)layer * 4096;
        u64 wcA[16], wcB[16];
#pragma unroll
        for (int k = 0; k < 16; ++k) {
            float2 r0 = *reinterpret_cast<const float2*>(wbase + (2 * k) * 128 + jA);
            float2 r1 = *reinterpret_cast<const float2*>(wbase + (2 * k + 1) * 128 + jA);
            wcA[k] = pack2(r0.x, r1.x);
            wcB[k] = pack2(r0.y, r1.y);
        }
        float bjA = fb1[layer * 128 + jA], bjB = fb1[layer * 128 + jB];
        int rbase = half * 16;
#pragma unroll 2
        for (int rr = 0; rr < 16; ++rr) {
            int r = rbase + rr;
            const u64* xq = reinterpret_cast<const u64*>(Xs + r * 32);
            u64 aA = 0ull, aB = 0ull;
#pragma unroll
            for (int k = 0; k < 16; ++k) {
                u64 x = xq[k];
                aA = fma2(x, wcA[k], aA);
                aB = fma2(x, wcB[k], aB);
            }
            float2 sA = unpack2(aA), sB = unpack2(aB);
            float xA = sA.x + sA.y + bjA;
            float xB = sB.x + sB.y + bjB;
            HsT[jA * 34 + r] = 0.5f * xA * (1.0f + erff(xA * 0.70710678118654752f));
            HsT[jB * 34 + r] = 0.5f * xB * (1.0f + erff(xB * 0.70710678118654752f));
        }
    }
    __syncthreads();

    {
        int rt = tid >> 3, dt = tid & 7;
        int r0 = rt * 2, d0 = dt * 4;
        u64 a00 = 0ull, a01 = 0ull, a10 = 0ull, a11 = 0ull;
#pragma unroll 4
        for (int j = 0; j < 128; ++j) {
            float2 h2 = *reinterpret_cast<const float2*>(HsT + j * 34 + r0);
            ulonglong2 u = *reinterpret_cast<const ulonglong2*>(Us + j * 32 + d0);
            u64 h0 = pack2(h2.x, h2.x), h1 = pack2(h2.y, h2.y);
            a00 = fma2(h0, u.x, a00);
            a01 = fma2(h0, u.y, a01);
            a10 = fma2(h1, u.x, a10);
            a11 = fma2(h1, u.y, a11);
        }
        float* Vout = (vout_sel == 1) ? g_VA : g_VB;
        float4 c4 = *reinterpret_cast<const float4*>(Us + 128 * 32 + d0);
        float2 p00 = unpack2(a00), p01 = unpack2(a01);
        float2 p10 = unpack2(a10), p11 = unpack2(a11);
        *reinterpret_cast<float4*>(Vout + ((size_t)(b * 2048 + n0 + r0)) * 32 + d0) =
            make_float4(p00.x + c4.x, p00.y + c4.y, p01.x + c4.z, p01.y + c4.w);
        *reinterpret_cast<float4*>(Vout + ((size_t)(b * 2048 + n0 + r0 + 1)) * 32 + d0) =
            make_float4(p10.x + c4.x, p10.y + c4.y, p11.x + c4.z, p11.y + c4.w);
    }
}

// ---------- final projection, fused partial + completion (ticket) ----------
__global__ __launch_bounds__(256) void k_fproj(const float* __restrict__ Wf,
                                               const float* __restrict__ bf,
                                               float* __restrict__ out) {
    __shared__ float wsum[8][10];
    __shared__ int s_last;
    int b = blockIdx.y, ch = blockIdx.x, tid = threadIdx.x;
    int lane = tid & 31, w = tid >> 5;
    float acc[10];
#pragma unroll
    for (int c = 0; c < 10; ++c) acc[c] = 0.f;
    const float* Vb = g_VB + (size_t)b * 65536 + ch * 2048;
#pragma unroll
    for (int q = 0; q < 8; ++q) {
        int k = q * 256 + tid;
        float v = Vb[k];
        const float* wr = Wf + (size_t)(ch * 2048 + k) * 10;
#pragma unroll
        for (int c = 0; c < 10; ++c) acc[c] += v * wr[c];
    }
#pragma unroll
    for (int c = 0; c < 10; ++c) {
#pragma unroll
        for (int s = 16; s > 0; s >>= 1) acc[c] += __shfl_down_sync(0xffffffffu, acc[c], s);
        if (lane == 0) wsum[w][c] = acc[c];
    }
    __syncthreads();
    if (tid < 10) {
        float s = 0.f;
#pragma unroll
        for (int ww = 0; ww < 8; ++ww) s += wsum[ww][tid];
        g_partF[((size_t)(b * 32 + ch)) * 10 + tid] = s;
    }
    __threadfence();
    __syncthreads();
    if (tid == 0) {
        unsigned prev = atomicAdd(&g_tick, 1u);
        s_last = (prev == 511u) ? 1 : 0;
    }
    __syncthreads();
    if (s_last) {
        __threadfence();
        if (tid < 160) {
            int bb = tid / 10, c = tid % 10;
            float s = bf[c];
#pragma unroll
            for (int cc = 0; cc < 32; ++cc) s += g_partF[((size_t)(bb * 32 + cc)) * 10 + c];
            out[tid] = s;
        }
        if (tid == 0) g_tick = 0u;
    }
}

extern "C" void kernel_launch(void* const* d_in, const int* in_sizes, int n_in,
                              void* d_out, int out_size) {
    const int*   data = (const int*)  d_in[0];
    const float* emb  = (const float*)d_in[1];
    const float* fw1  = (const float*)d_in[2];
    const float* fb1  = (const float*)d_in[3];
    const float* fw2  = (const float*)d_in[4];
    const float* fb2  = (const float*)d_in[5];
    const float* Wf   = (const float*)d_in[6];
    const float* bf   = (const float*)d_in[7];
    float* out = (float*)d_out;

    k_gather<<<1024, 256>>>(data, emb);

    // layers i = 3,2,1,0 ; V ping-pong: X -> VA -> VB -> VA -> VB
    int vin = 0;
    for (int it = 0; it < 4; ++it) {
        int layer = 3 - it;
        int vout = (vin == 1) ? 2 : 1;
        k_upart<<<dim3(16, 16), 256>>>(fw2, fb2, vin, layer);
        k_ured<<<129, 512>>>();
        k_vupd<<<dim3(64, 16), 128>>>(fw1, fb1, vout, layer);
        vin = vout;
    }

    k_fproj<<<dim3(32, 16), 256>>>(Wf, bf, out);
}